// round 10
// baseline (speedup 1.0000x reference)
#include <cuda_runtime.h>
#include <cuda_fp16.h>
#include <cstdint>

// ---------------- problem constants ----------------
#define NB   32
#define IC   64
#define OCH  128
#define HH   128
#define WW   128
#define OH   126
#define OW   126

// smem: four x rows (oh0..oh0+3) + two weight-tap buffers, rows stride XSTR halves
#define XSTR     72
#define SX_ROWS  130
#define SX_BYTES (SX_ROWS * XSTR * 2)            // 18720
#define TAPB     (OCH * XSTR * 2)                // 18432 per tap
#define WB0      (4 * SX_BYTES)                  // 74880
#define WB1      (4 * SX_BYTES + TAPB)
#define SMEM_BYTES (4 * SX_BYTES + 2 * TAPB)     // 111744

// pre-converted fp16 weights: g_wh[kk][oc][ic/2] as half2 (row = oc, 64 halves)
__device__ __half2 g_wh[9 * OCH * (IC / 2)];
// pre-transposed fp16 x: g_xh[n][h][w][ic/2]  (ic contiguous)
__device__ __half2 g_xh[(size_t)NB * HH * WW * (IC / 2)];

__global__ void wt_half_kernel(const float* __restrict__ wg) {
    int i = blockIdx.x * 256 + threadIdx.x;          // over 9*128*32
    if (i < 9 * OCH * (IC / 2)) {
        int kk  = i / (OCH * 32);
        int r   = i - kk * (OCH * 32);
        int oc  = r >> 5;
        int ic  = (r & 31) * 2;
        float v0 = wg[(oc * IC + ic)     * 9 + kk];
        float v1 = wg[(oc * IC + ic + 1) * 9 + kk];
        g_wh[i] = __floats2half2_rn(v0, v1);
    }
}

// transpose + fp16 convert: x[n][ic][h][w] -> g_xh[n][h][w][ic]
__global__ void x_half_kernel(const float* __restrict__ x) {
    __shared__ __half s[128 * 66];
    const int h = blockIdx.x, n = blockIdx.y, tid = threadIdx.x;
    const float* src = x + ((size_t)n * IC * HH + h) * WW;
    #pragma unroll
    for (int i = 0; i < 32; i++) {
        int idx = tid + i * 256;
        int ic = idx >> 7, w = idx & 127;
        s[w * 66 + ic] = __float2half_rn(src[(size_t)ic * (HH * WW) + w]);
    }
    __syncthreads();
    __half2* dst = g_xh + ((size_t)(n * HH + h)) * (WW * 32);
    #pragma unroll
    for (int i = 0; i < 16; i++) {
        int idx = tid + i * 256;
        int w = idx >> 5, icp = idx & 31;
        dst[w * 32 + icp] = *(__half2*)&s[w * 66 + 2 * icp];
    }
}

__device__ __forceinline__ uint32_t smem_u32(const void* p) {
    uint32_t a;
    asm("{ .reg .u64 t; cvta.to.shared.u64 t, %1; cvt.u32.u64 %0, t; }"
        : "=r"(a) : "l"(p));
    return a;
}
__device__ __forceinline__ void cp16(uint32_t dst, const void* src) {
    asm volatile("cp.async.cg.shared.global [%0], [%1], 16;"
                 :: "r"(dst), "l"(src));
}
__device__ __forceinline__ void ldsm_x4(uint32_t& r0, uint32_t& r1,
                                        uint32_t& r2, uint32_t& r3,
                                        uint32_t addr) {
    asm volatile("ldmatrix.sync.aligned.m8n8.x4.shared.b16 {%0,%1,%2,%3}, [%4];"
                 : "=r"(r0), "=r"(r1), "=r"(r2), "=r"(r3) : "r"(addr));
}
__device__ __forceinline__ void hmma16816(float* c, const uint32_t* a,
                                          uint32_t b0, uint32_t b1) {
    asm volatile(
        "mma.sync.aligned.m16n8k16.row.col.f32.f16.f16.f32 "
        "{%0,%1,%2,%3}, {%4,%5,%6,%7}, {%8,%9}, {%0,%1,%2,%3};"
        : "+f"(c[0]), "+f"(c[1]), "+f"(c[2]), "+f"(c[3])
        : "r"(a[0]), "r"(a[1]), "r"(a[2]), "r"(a[3]), "r"(b0), "r"(b1));
}

__global__ void __launch_bounds__(512, 1)
conv_hmma_kernel(const float* __restrict__ bias,
                 float* __restrict__ out)
{
    extern __shared__ char smem[];
    const uint32_t sbase = smem_u32(smem);

    const int tid  = threadIdx.x;
    const int lane = tid & 31;
    const int warp = tid >> 5;       // 0..15
    const int g    = lane >> 2;      // group id 0..7
    const int t    = lane & 3;       // thread in group

    const int warp_m = warp & 3;     // 4 warps over M=256 (64 each)
    const int warp_n = warp >> 2;    // 4 warps over N=128 (32 each)

    const int oh0 = blockIdx.x * 2;  // this CTA: output rows oh0, oh0+1
    const int n   = blockIdx.y;

    float c[4][4][4];                // [m-tile][n-tile][reg]
    #pragma unroll
    for (int i = 0; i < 4; i++)
        #pragma unroll
        for (int j = 0; j < 4; j++)
            #pragma unroll
            for (int r = 0; r < 4; r++)
                c[i][j][r] = 0.f;

    // zero halo w=128,129 of all 4 x rows (4 rows x 2 w x 32 u32 = 256)
    if (tid < 256) {
        int row = tid >> 6;
        int r   = (tid >> 5) & 1;
        int cc  = tid & 31;
        *(uint32_t*)(smem + row * SX_BYTES +
                     (128 + r) * (XSTR * 2) + cc * 4) = 0;
    }

    const uint32_t woff[2] = {WB0, WB1};
    auto stage_w = [&](uint32_t off, int kk) {
        const __half* wr = (const __half*)g_wh + (size_t)kk * (OCH * IC);
        #pragma unroll
        for (int i = 0; i < 2; i++) {
            int idx = tid + i * 512;
            int oc = idx >> 3, cc = idx & 7;
            cp16(sbase + off + (uint32_t)((oc * XSTR + cc * 8) * 2),
                 wr + oc * IC + cc * 8);
        }
    };

    // ldmatrix per-lane invariant offsets (bytes)
    const int l7 = lane & 7;
    const uint32_t a_lane =
        (uint32_t)(((l7 + ((lane >> 3) & 1) * 8) * XSTR + ((lane >> 4) & 1) * 8) * 2);
    const uint32_t b_lane =
        (uint32_t)(((l7 + ((lane >> 4) & 1) * 8) * XSTR + ((lane >> 3) & 1) * 8) * 2);

    // ---- prologue: stage 4 x rows + w tap0 (group0), w tap1 (group1)
    {
        const __half* xr0 = (const __half*)g_xh +
                            ((size_t)(n * HH + oh0)) * (WW * IC);
        #pragma unroll
        for (int i = 0; i < 8; i++) {
            int idx = tid + i * 512;          // 0..4095
            int row = idx >> 10;
            int rem = idx & 1023;
            int w = rem >> 3, cc = rem & 7;
            cp16(sbase + (uint32_t)(row * SX_BYTES + (w * XSTR + cc * 8) * 2),
                 xr0 + (size_t)row * (WW * IC) + w * IC + cc * 8);
        }
    }
    stage_w(WB0, 0);
    asm volatile("cp.async.commit_group;" ::: "memory");
    stage_w(WB1, 1);
    asm volatile("cp.async.commit_group;" ::: "memory");

    // ---- 9-tap pipelined mainloop
    #pragma unroll
    for (int it = 0; it < 9; it++) {
        const int kh = it / 3, kw = it % 3;
        // warp_m 0,1 -> x row kh (m-halves 0,64); warp_m 2,3 -> x row kh+1
        const uint32_t aBase = sbase + a_lane +
            (uint32_t)((kh + (warp_m >> 1)) * SX_BYTES +
                       ((warp_m & 1) * 64 + kw) * (XSTR * 2));
        const uint32_t bBase = sbase + woff[it & 1] + b_lane +
                               (uint32_t)(warp_n * 32 * (XSTR * 2));

        asm volatile("cp.async.wait_group 1;" ::: "memory");
        __syncthreads();

        #pragma unroll
        for (int ks = 0; ks < 4; ks++) {
            uint32_t a[4][4];
            #pragma unroll
            for (int i = 0; i < 4; i++)
                ldsm_x4(a[i][0], a[i][1], a[i][2], a[i][3],
                        aBase + (uint32_t)((i * 16 * XSTR + ks * 16) * 2));

            #pragma unroll
            for (int jp = 0; jp < 2; jp++) {
                uint32_t b0, b1, b2, b3;
                ldsm_x4(b0, b1, b2, b3,
                        bBase + (uint32_t)((jp * 16 * XSTR + ks * 16) * 2));
                #pragma unroll
                for (int i = 0; i < 4; i++) {
                    hmma16816(c[i][jp * 2],     a[i], b0, b1);
                    hmma16816(c[i][jp * 2 + 1], a[i], b2, b3);
                }
            }
        }

        __syncthreads();

        if (it < 7)
            stage_w(woff[it & 1], it + 2);    // reuse just-freed W buffer
        asm volatile("cp.async.commit_group;" ::: "memory");
    }

    // ---- epilogue: bias, -0.7, Mish ----
    const int oh = oh0 + (warp_m >> 1);
    #pragma unroll
    for (int j = 0; j < 4; j++) {
        const int oc0 = warp_n * 32 + j * 8 + 2 * t;
        const float b0 = bias[oc0]     - 0.7f;
        const float b1 = bias[oc0 + 1] - 0.7f;
        #pragma unroll
        for (int i = 0; i < 4; i++) {
            #pragma unroll
            for (int r = 0; r < 4; r++) {
                const int m = (warp_m & 1) * 64 + i * 16 + g + ((r & 2) ? 8 : 0);
                if (m >= OW) continue;
                const int oc = oc0 + (r & 1);
                float v = c[i][j][r] + ((r & 1) ? b1 : b0);
                float e = __expf(fminf(v, 15.f));
                float s = 1.f + e; s = s * s;
                out[((size_t)(n * OCH + oc) * OH + oh) * OW + m] =
                    v * __fdividef(s - 1.f, s + 1.f);
            }
        }
    }
}

extern "C" void kernel_launch(void* const* d_in, const int* in_sizes, int n_in,
                              void* d_out, int out_size) {
    const float* x  = (const float*)d_in[0];
    const float* w  = (const float*)d_in[1];
    const float* b  = (const float*)d_in[2];
    float* out      = (float*)d_out;

    wt_half_kernel<<<(9 * OCH * (IC / 2) + 255) / 256, 256>>>(w);
    {
        dim3 tg(HH, NB);
        x_half_kernel<<<tg, 256>>>(x);
    }

    cudaFuncSetAttribute(conv_hmma_kernel,
                         cudaFuncAttributeMaxDynamicSharedMemorySize, SMEM_BYTES);
    dim3 grid(OH / 2, NB);   // 63 x 32 CTAs, two oh rows each
    conv_hmma_kernel<<<grid, 512, SMEM_BYTES>>>(b, out);
}

// round 11
// speedup vs baseline: 1.1322x; 1.1322x over previous
#include <cuda_runtime.h>
#include <cuda_fp16.h>
#include <cstdint>

// ---------------- problem constants ----------------
#define NB   32
#define IC   64
#define OCH  128
#define HH   128
#define WW   128
#define OH   126
#define OW   126

// smem: two x buffers + THREE weight-tap buffers, all rows stride XSTR halves
#define XSTR     72
#define SX_ROWS  130
#define SX_BYTES (SX_ROWS * XSTR * 2)            // 18720
#define TAPB     (OCH * XSTR * 2)                // 18432 per tap
#define XB0      0
#define XB1      SX_BYTES
#define WB0      (2 * SX_BYTES)
#define WB1      (2 * SX_BYTES + TAPB)
#define WB2      (2 * SX_BYTES + 2 * TAPB)
#define SMEM_BYTES (2 * SX_BYTES + 3 * TAPB)     // 92736

// pre-converted fp16 weights: g_wh[kk][oc][ic/2] as half2 (row = oc, 64 halves)
__device__ __half2 g_wh[9 * OCH * (IC / 2)];
// pre-transposed fp16 x: g_xh[n][h][w][ic/2]  (ic contiguous)
__device__ __half2 g_xh[(size_t)NB * HH * WW * (IC / 2)];

__global__ void wt_half_kernel(const float* __restrict__ wg) {
    int i = blockIdx.x * 256 + threadIdx.x;          // over 9*128*32
    if (i < 9 * OCH * (IC / 2)) {
        int kk  = i / (OCH * 32);
        int r   = i - kk * (OCH * 32);
        int oc  = r >> 5;
        int ic  = (r & 31) * 2;
        float v0 = wg[(oc * IC + ic)     * 9 + kk];
        float v1 = wg[(oc * IC + ic + 1) * 9 + kk];
        g_wh[i] = __floats2half2_rn(v0, v1);
    }
}

// transpose + fp16 convert: x[n][ic][h][w] -> g_xh[n][h][w][ic]
__global__ void x_half_kernel(const float* __restrict__ x) {
    __shared__ __half s[128 * 66];
    const int h = blockIdx.x, n = blockIdx.y, tid = threadIdx.x;
    const float* src = x + ((size_t)n * IC * HH + h) * WW;
    #pragma unroll
    for (int i = 0; i < 32; i++) {
        int idx = tid + i * 256;
        int ic = idx >> 7, w = idx & 127;
        s[w * 66 + ic] = __float2half_rn(src[(size_t)ic * (HH * WW) + w]);
    }
    __syncthreads();
    __half2* dst = g_xh + ((size_t)(n * HH + h)) * (WW * 32);
    #pragma unroll
    for (int i = 0; i < 16; i++) {
        int idx = tid + i * 256;
        int w = idx >> 5, icp = idx & 31;
        dst[w * 32 + icp] = *(__half2*)&s[w * 66 + 2 * icp];
    }
}

__device__ __forceinline__ uint32_t smem_u32(const void* p) {
    uint32_t a;
    asm("{ .reg .u64 t; cvta.to.shared.u64 t, %1; cvt.u32.u64 %0, t; }"
        : "=r"(a) : "l"(p));
    return a;
}
__device__ __forceinline__ void cp16(uint32_t dst, const void* src) {
    asm volatile("cp.async.cg.shared.global [%0], [%1], 16;"
                 :: "r"(dst), "l"(src));
}
__device__ __forceinline__ void ldsm_x4(uint32_t& r0, uint32_t& r1,
                                        uint32_t& r2, uint32_t& r3,
                                        uint32_t addr) {
    asm volatile("ldmatrix.sync.aligned.m8n8.x4.shared.b16 {%0,%1,%2,%3}, [%4];"
                 : "=r"(r0), "=r"(r1), "=r"(r2), "=r"(r3) : "r"(addr));
}
__device__ __forceinline__ void hmma16816(float* c, const uint32_t* a,
                                          uint32_t b0, uint32_t b1) {
    asm volatile(
        "mma.sync.aligned.m16n8k16.row.col.f32.f16.f16.f32 "
        "{%0,%1,%2,%3}, {%4,%5,%6,%7}, {%8,%9}, {%0,%1,%2,%3};"
        : "+f"(c[0]), "+f"(c[1]), "+f"(c[2]), "+f"(c[3])
        : "r"(a[0]), "r"(a[1]), "r"(a[2]), "r"(a[3]), "r"(b0), "r"(b1));
}

__global__ void __launch_bounds__(256, 2)
conv_hmma_kernel(const float* __restrict__ bias,
                 float* __restrict__ out)
{
    extern __shared__ char smem[];
    const uint32_t sbase = smem_u32(smem);

    const int tid  = threadIdx.x;
    const int lane = tid & 31;
    const int warp = tid >> 5;
    const int g    = lane >> 2;      // group id 0..7
    const int t    = lane & 3;       // thread in group

    const int warp_m = warp & 1;     // 2 warps over M=128 (64 each)
    const int warp_n = warp >> 1;    // 4 warps over N=128 (32 each)

    const int oh = blockIdx.x;
    const int n  = blockIdx.y;

    float c[4][4][4];                // [m-tile][n-tile][reg]
    #pragma unroll
    for (int i = 0; i < 4; i++)
        #pragma unroll
        for (int j = 0; j < 4; j++)
            #pragma unroll
            for (int r = 0; r < 4; r++)
                c[i][j][r] = 0.f;

    // zero halo rows w=128,129 of BOTH x buffers (64 halves = 32 u32 per row)
    if (tid < 128) {
        int bsel = tid >> 6;
        int r    = (tid >> 5) & 1;
        int cc   = tid & 31;
        *(uint32_t*)(smem + (bsel ? XB1 : XB0) +
                     (128 + r) * (XSTR * 2) + cc * 4) = 0;
    }

    const uint32_t xoff[2] = {XB0, XB1};
    const uint32_t woff[3] = {WB0, WB1, WB2};
    auto stage_x = [&](uint32_t off, int ih) {
        const __half* xr = (const __half*)g_xh +
                           ((size_t)(n * HH + ih)) * (WW * IC);
        #pragma unroll
        for (int i = 0; i < 4; i++) {
            int idx = tid + i * 256;
            int w = idx >> 3, cc = idx & 7;
            cp16(sbase + off + (uint32_t)((w * XSTR + cc * 8) * 2),
                 xr + w * IC + cc * 8);
        }
    };
    auto stage_w = [&](uint32_t off, int kk) {
        const __half* wr = (const __half*)g_wh + (size_t)kk * (OCH * IC);
        #pragma unroll
        for (int i = 0; i < 4; i++) {
            int idx = tid + i * 256;
            int oc = idx >> 3, cc = idx & 7;
            cp16(sbase + off + (uint32_t)((oc * XSTR + cc * 8) * 2),
                 wr + oc * IC + cc * 8);
        }
    };

    // ldmatrix per-lane invariant offsets (bytes)
    const int l7 = lane & 7;
    const uint32_t a_lane =
        (uint32_t)(((l7 + ((lane >> 3) & 1) * 8) * XSTR + ((lane >> 4) & 1) * 8) * 2);
    const uint32_t b_lane =
        (uint32_t)(((l7 + ((lane >> 4) & 1) * 8) * XSTR + ((lane >> 3) & 1) * 8) * 2);

    // ---- pipeline prologue: group0 = tap0 + x row kh0 ; group1 = tap1
    stage_x(XB0, oh);
    stage_w(WB0, 0);
    asm volatile("cp.async.commit_group;" ::: "memory");
    stage_w(WB1, 1);
    asm volatile("cp.async.commit_group;" ::: "memory");

    // ---- 9-tap pipelined mainloop (3-deep W ring, ONE sync per tap)
    #pragma unroll
    for (int it = 0; it < 9; it++) {
        const int kh = it / 3, kw = it % 3;
        const uint32_t aBase = sbase + xoff[kh & 1] + a_lane +
                               (uint32_t)((warp_m * 64 + kw) * XSTR * 2);
        const uint32_t bBase = sbase + woff[it % 3] + b_lane +
                               (uint32_t)(warp_n * 32 * XSTR * 2);

        asm volatile("cp.async.wait_group 1;" ::: "memory");
        __syncthreads();
        // Buffer W[(it+2)%3] was last READ in iteration it-1; all warps have
        // since passed the barrier above -> safe to overwrite now, overlapped
        // with this tap's compute.
        if (it < 7) {
            const int kk2 = it + 2;
            if (kk2 % 3 == 0)                    // new kh row needed
                stage_x(xoff[(kk2 / 3) & 1], oh + kk2 / 3);
            stage_w(woff[kk2 % 3], kk2);
        }
        asm volatile("cp.async.commit_group;" ::: "memory");

        #pragma unroll
        for (int ks = 0; ks < 4; ks++) {
            uint32_t a[4][4];
            #pragma unroll
            for (int i = 0; i < 4; i++)
                ldsm_x4(a[i][0], a[i][1], a[i][2], a[i][3],
                        aBase + (uint32_t)((i * 16 * XSTR + ks * 16) * 2));

            #pragma unroll
            for (int jp = 0; jp < 2; jp++) {
                uint32_t b0, b1, b2, b3;
                ldsm_x4(b0, b1, b2, b3,
                        bBase + (uint32_t)((jp * 16 * XSTR + ks * 16) * 2));
                #pragma unroll
                for (int i = 0; i < 4; i++) {
                    hmma16816(c[i][jp * 2],     a[i], b0, b1);
                    hmma16816(c[i][jp * 2 + 1], a[i], b2, b3);
                }
            }
        }
    }

    // ---- epilogue: bias, -0.7, Mish ----
    #pragma unroll
    for (int j = 0; j < 4; j++) {
        const int oc0 = warp_n * 32 + j * 8 + 2 * t;
        const float b0 = bias[oc0]     - 0.7f;
        const float b1 = bias[oc0 + 1] - 0.7f;
        #pragma unroll
        for (int i = 0; i < 4; i++) {
            #pragma unroll
            for (int r = 0; r < 4; r++) {
                const int m  = warp_m * 64 + i * 16 + g + ((r & 2) ? 8 : 0);
                if (m >= OW) continue;
                const int oc = oc0 + (r & 1);
                float v = c[i][j][r] + ((r & 1) ? b1 : b0);
                float e = __expf(fminf(v, 15.f));
                float s = 1.f + e; s = s * s;
                out[((size_t)(n * OCH + oc) * OH + oh) * OW + m] =
                    v * __fdividef(s - 1.f, s + 1.f);
            }
        }
    }
}

extern "C" void kernel_launch(void* const* d_in, const int* in_sizes, int n_in,
                              void* d_out, int out_size) {
    const float* x  = (const float*)d_in[0];
    const float* w  = (const float*)d_in[1];
    const float* b  = (const float*)d_in[2];
    float* out      = (float*)d_out;

    wt_half_kernel<<<(9 * OCH * (IC / 2) + 255) / 256, 256>>>(w);
    {
        dim3 tg(HH, NB);
        x_half_kernel<<<tg, 256>>>(x);
    }

    cudaFuncSetAttribute(conv_hmma_kernel,
                         cudaFuncAttributeMaxDynamicSharedMemorySize, SMEM_BYTES);
    dim3 grid(OH, NB);   // 126 x 32 CTAs, one (n, oh) each
    conv_hmma_kernel<<<grid, 256, SMEM_BYTES>>>(b, out);
}